// round 16
// baseline (speedup 1.0000x reference)
#include <cuda_runtime.h>

// QuantumLinear closed form — single-wave + software-pipelined loads.
//
// Closed form (X-basis Walsh collapse), a_q = x_q + w0_q, b_q = w1_q:
//   z0 = 1/2[cos(a1+a3)cos(a0+b3)cos(b1+b2) + cos(a1-a3)cos(a0-b3)cos(b1-b2)]
//   z1 = 1/2 cos(a3)[cos(a0+a2)cos(b0+b1) + cos(a0-a2)cos(b0-b1)]
//   z2 = 1/2 cos(b0)[cos(a1+a3)cos(b1+b2) + cos(a1-a3)cos(b1-b2)]
//   z3 = 1/2[cos(b2+b3)cos(a2+b0)cos(a0+b1) + cos(b2-b3)cos(a2-b0)cos(a0-b1)]
//
// R9 (front-batch, 40 regs): best kernel 7.97us, but 6 blocks/SM -> 912-slot
// wave < 1024 blocks -> 112-block straggler wave. R13 (32-reg JIT loads):
// 11.3us under profiling — serial loads are worse than the tail.
// This round: rotating 3-buffer load pipeline (loads stay >=1 sim ahead of
// compute) at <=36 regs via __launch_bounds__(256,7): 7 blocks/SM -> all
// 1024 blocks resident in ONE wave, ILP preserved.

#define QL_BDIM 256
#define SPT 4            // sims per thread

__global__ __launch_bounds__(QL_BDIM, 7)   // <=36 regs -> 7 blocks/SM, 1 wave
void ql_closed_kernel(const float4* __restrict__ x4,
                      const float4* __restrict__ w4,
                      float4* __restrict__ out4,
                      int nthreads)          // = total_sims / SPT, multiple of 256
{
    int t = blockIdx.x * QL_BDIM + threadIdx.x;
    if (t >= nthreads) return;
    int c = t & 255;                          // circuit index, same for all SPT sims

    const float4* xp = x4 + t;
    float4*       op = out4 + t;

    float4 w0 = w4[2 * c];
    float4 w1 = w4[2 * c + 1];

    // first two x loads in flight before any MUFU work
    float4 xa = xp[0];
    float4 xb = xp[nthreads];

    float b0 = w1.x, b1 = w1.y, b2 = w1.z, b3 = w1.w;

    // weight-only constants (1/2 folded in)
    float h12p = 0.5f * __cosf(b1 + b2);
    float h12m = 0.5f * __cosf(b1 - b2);
    float h01p = 0.5f * __cosf(b0 + b1);
    float h01m = 0.5f * __cosf(b0 - b1);
    float cb0  = __cosf(b0);
    float g12p = cb0 * h12p;                  // for z2
    float g12m = cb0 * h12m;
    float h23p = 0.5f * __cosf(b2 + b3);
    float h23m = 0.5f * __cosf(b2 - b3);

    auto sim = [&](float4 xv) -> float4 {
        float a0 = xv.x + w0.x;
        float a1 = xv.y + w0.y;
        float a2 = xv.z + w0.z;
        float a3 = xv.w + w0.w;

        float ca13p = __cosf(a1 + a3);
        float ca13m = __cosf(a1 - a3);

        float c0p = __cosf(a0 + b3);
        float c0m = __cosf(a0 - b3);
        float z0 = fmaf(ca13m * c0m, h12m, (ca13p * c0p) * h12p);

        float ca3  = __cosf(a3);
        float c02p = __cosf(a0 + a2);
        float c02m = __cosf(a0 - a2);
        float z1 = ca3 * fmaf(c02m, h01m, c02p * h01p);

        float z2 = fmaf(ca13m, g12m, ca13p * g12p);

        float c20p = __cosf(a2 + b0);
        float c20m = __cosf(a2 - b0);
        float c01p = __cosf(a0 + b1);
        float c01m = __cosf(a0 - b1);
        float z3 = fmaf(h23m * c20m, c01m, (h23p * c20p) * c01p);

        return make_float4(z0, z1, z2, z3);
    };

    // rotating 3-buffer pipeline: next load issues before current compute
    float4 xc = xp[2 * nthreads];
    float4 r0 = sim(xa);
    op[0] = r0;

    xa = xp[3 * nthreads];                    // last load in flight
    float4 r1 = sim(xb);
    op[nthreads] = r1;

    float4 r2 = sim(xc);
    op[2 * nthreads] = r2;

    float4 r3 = sim(xa);
    op[3 * nthreads] = r3;
}

extern "C" void kernel_launch(void* const* d_in, const int* in_sizes, int n_in,
                              void* d_out, int out_size)
{
    const float4* x4 = (const float4*)d_in[0];   // x: (4096, 1024) f32
    const float4* w4 = (const float4*)d_in[1];   // weights: (256, 2, 4) f32
    float4* o4 = (float4*)d_out;                 // out: (4096, 1024) f32

    int total = in_sizes[0] / 4;                 // 1,048,576 sims
    int nthreads = total / SPT;                  // 262,144 (multiple of 256)
    int grid = (nthreads + QL_BDIM - 1) / QL_BDIM;   // 1024 blocks, 1 wave @7/SM
    ql_closed_kernel<<<grid, QL_BDIM>>>(x4, w4, o4, nthreads);
}